// round 8
// baseline (speedup 1.0000x reference)
#include <cuda_runtime.h>

#define SEQ   4096
#define BATCH 4096
#define NIN   2
#define HID   8
#define CTAS  128
#define BPC   (BATCH / CTAS)   // 32 batches per CTA
#define LPB   4                // lanes per batch (each lane owns 2 h values)
#define TPB   (BPC * LPB)      // 128 threads

typedef unsigned long long u64;

// MUFU.TANH: single-instruction tanh (sm_75+), max abs err ~2^-10.7
__device__ __forceinline__ float tanhap_(float x) {
    float y; asm("tanh.approx.f32 %0, %1;" : "=f"(y) : "f"(x)); return y;
}

// Pack two floats into a b64 register pair.
__device__ __forceinline__ u64 pk2(float lo, float hi) {
    u64 d;
    asm("mov.b64 %0, {%1, %2};" : "=l"(d)
        : "r"(__float_as_uint(lo)), "r"(__float_as_uint(hi)));
    return d;
}
__device__ __forceinline__ void upk2(u64 v, float& lo, float& hi) {
    unsigned a, b;
    asm("mov.b64 {%0, %1}, %2;" : "=r"(a), "=r"(b) : "l"(v));
    lo = __uint_as_float(a); hi = __uint_as_float(b);
}

// Packed fp32x2 ops on b64 carriers — single SASS instruction each.
__device__ __forceinline__ u64 ffma2(u64 a, u64 b, u64 c) {
    u64 d; asm("fma.rn.f32x2 %0, %1, %2, %3;" : "=l"(d) : "l"(a), "l"(b), "l"(c)); return d;
}
__device__ __forceinline__ u64 fmul2(u64 a, u64 b) {
    u64 d; asm("mul.rn.f32x2 %0, %1, %2;" : "=l"(d) : "l"(a), "l"(b)); return d;
}
__device__ __forceinline__ u64 fadd2(u64 a, u64 b) {
    u64 d; asm("add.rn.f32x2 %0, %1, %2;" : "=l"(d) : "l"(a), "l"(b)); return d;
}

__global__ void __launch_bounds__(TPB) lstm_kernel(
    const float* __restrict__ x,
    const float* __restrict__ h0,
    const float* __restrict__ c0,
    const float* __restrict__ W_ih,
    const float* __restrict__ W_hh,
    const float* __restrict__ b_ih,
    const float* __restrict__ b_hh,
    float* __restrict__ out)
{
    const int tid = threadIdx.x;
    const int g   = tid >> 2;        // batch group within CTA, 0..31
    const int q   = tid & 3;         // quarter-lane, owns h[2q], h[2q+1]
    const int b   = blockIdx.x * BPC + g;
    const int o0  = 2 * q, o1 = 2 * q + 1;

    // Activation plan (all via single-instruction MUFU.TANH):
    //   sigmoid(u) = 0.5*tanh(u/2) + 0.5  -> fold the 1/2 into rows i,f,o
    //   tanh(u)                            -> row g unscaled
    const float si = 0.5f, sf = 0.5f, sg = 1.0f, so = 0.5f;

    // Pair-packed weights: lane accumulates gate G for BOTH owned outputs as
    // one f32x2 pair (G[o0], G[o1]). 4 gates x 8 k = 32 u64 weight carriers.
    u64 wi[HID], wf[HID], wg[HID], wo[HID];
    #pragma unroll
    for (int k = 0; k < HID; k++) {
        wi[k] = pk2(si * W_hh[(0*HID + o0) * HID + k], si * W_hh[(0*HID + o1) * HID + k]);
        wf[k] = pk2(sf * W_hh[(1*HID + o0) * HID + k], sf * W_hh[(1*HID + o1) * HID + k]);
        wg[k] = pk2(sg * W_hh[(2*HID + o0) * HID + k], sg * W_hh[(2*HID + o1) * HID + k]);
        wo[k] = pk2(so * W_hh[(3*HID + o0) * HID + k], so * W_hh[(3*HID + o1) * HID + k]);
    }
    u64 wix0 = pk2(si * W_ih[(0*HID + o0) * NIN + 0], si * W_ih[(0*HID + o1) * NIN + 0]);
    u64 wix1 = pk2(si * W_ih[(0*HID + o0) * NIN + 1], si * W_ih[(0*HID + o1) * NIN + 1]);
    u64 wfx0 = pk2(sf * W_ih[(1*HID + o0) * NIN + 0], sf * W_ih[(1*HID + o1) * NIN + 0]);
    u64 wfx1 = pk2(sf * W_ih[(1*HID + o0) * NIN + 1], sf * W_ih[(1*HID + o1) * NIN + 1]);
    u64 wgx0 = pk2(sg * W_ih[(2*HID + o0) * NIN + 0], sg * W_ih[(2*HID + o1) * NIN + 0]);
    u64 wgx1 = pk2(sg * W_ih[(2*HID + o0) * NIN + 1], sg * W_ih[(2*HID + o1) * NIN + 1]);
    u64 wox0 = pk2(so * W_ih[(3*HID + o0) * NIN + 0], so * W_ih[(3*HID + o1) * NIN + 0]);
    u64 wox1 = pk2(so * W_ih[(3*HID + o0) * NIN + 1], so * W_ih[(3*HID + o1) * NIN + 1]);
    u64 bi = pk2(si * (b_ih[0*HID + o0] + b_hh[0*HID + o0]), si * (b_ih[0*HID + o1] + b_hh[0*HID + o1]));
    u64 bf = pk2(sf * (b_ih[1*HID + o0] + b_hh[1*HID + o0]), sf * (b_ih[1*HID + o1] + b_hh[1*HID + o1]));
    u64 bg = pk2(sg * (b_ih[2*HID + o0] + b_hh[2*HID + o0]), sg * (b_ih[2*HID + o1] + b_hh[2*HID + o1]));
    u64 bo = pk2(so * (b_ih[3*HID + o0] + b_hh[3*HID + o0]), so * (b_ih[3*HID + o1] + b_hh[3*HID + o1]));

    // h exchange: duplicated (h,h) pairs, double-buffered; all producers and
    // consumers of a group's 64B region live in the same warp.
    __shared__ __align__(16) u64 sh[2][BPC][HID];

    float c_0 = c0[b * HID + o0];
    float c_1 = c0[b * HID + o1];
    float h_0 = h0[b * HID + o0];
    float h_1 = h0[b * HID + o1];
    {
        ulonglong2 hh;
        hh.x = pk2(h_0, h_0);
        hh.y = pk2(h_1, h_1);
        *(ulonglong2*)&sh[0][g][o0] = hh;
    }
    __syncwarp();

    const size_t xstride = (size_t)BATCH * NIN;
    const float* xbase = x + (size_t)b * NIN;
    auto ldx = [&](int s) -> float2 {
        int sc = s < SEQ ? s : (SEQ - 1);
        return *(const float2*)(xbase + (size_t)sc * xstride);
    };

    // x-projection (bias + W_ih*x) computed off the recurrence chain.
    u64 xpi, xpf, xpg, xpo;
    auto xproj = [&](float2 xv, u64& pi, u64& pf, u64& pg, u64& po) {
        u64 x0d = pk2(xv.x, xv.x);
        u64 x1d = pk2(xv.y, xv.y);
        pi = ffma2(wix1, x1d, ffma2(wix0, x0d, bi));
        pf = ffma2(wfx1, x1d, ffma2(wfx0, x0d, bf));
        pg = ffma2(wgx1, x1d, ffma2(wgx0, x0d, bg));
        po = ffma2(wox1, x1d, ffma2(wox0, x0d, bo));
    };

    float2 xa = ldx(1), xb = ldx(2), xc = ldx(3), xd = ldx(4);
    xproj(ldx(0), xpi, xpf, xpg, xpo);

    auto dostep = [&](float2 xnext, int rd) {
        // 4x LDS.128: eight duplicated h pairs for this batch group
        const ulonglong2* hp = (const ulonglong2*)&sh[rd][g][0];
        ulonglong2 p0 = hp[0], p1 = hp[1], p2 = hp[2], p3 = hp[3];

        // Fill the LDS latency window with next step's x projection
        u64 ni, nf, ng, no;
        xproj(xnext, ni, nf, ng, no);

        // Four gate-pair accumulators, each as two balanced FFMA2 trees
        u64 iA = ffma2(wi[0], p0.x, xpi);  u64 iB = fmul2(wi[1], p0.y);
        u64 fA = ffma2(wf[0], p0.x, xpf);  u64 fB = fmul2(wf[1], p0.y);
        u64 gA = ffma2(wg[0], p0.x, xpg);  u64 gB = fmul2(wg[1], p0.y);
        u64 oA = ffma2(wo[0], p0.x, xpo);  u64 oB = fmul2(wo[1], p0.y);

        iA = ffma2(wi[2], p1.x, iA);  iB = ffma2(wi[3], p1.y, iB);
        fA = ffma2(wf[2], p1.x, fA);  fB = ffma2(wf[3], p1.y, fB);
        gA = ffma2(wg[2], p1.x, gA);  gB = ffma2(wg[3], p1.y, gB);
        oA = ffma2(wo[2], p1.x, oA);  oB = ffma2(wo[3], p1.y, oB);

        iA = ffma2(wi[4], p2.x, iA);  iB = ffma2(wi[5], p2.y, iB);
        fA = ffma2(wf[4], p2.x, fA);  fB = ffma2(wf[5], p2.y, fB);
        gA = ffma2(wg[4], p2.x, gA);  gB = ffma2(wg[5], p2.y, gB);
        oA = ffma2(wo[4], p2.x, oA);  oB = ffma2(wo[5], p2.y, oB);

        iA = ffma2(wi[6], p3.x, iA);  iB = ffma2(wi[7], p3.y, iB);
        fA = ffma2(wf[6], p3.x, fA);  fB = ffma2(wf[7], p3.y, fB);
        gA = ffma2(wg[6], p3.x, gA);  gB = ffma2(wg[7], p3.y, gB);
        oA = ffma2(wo[6], p3.x, oA);  oB = ffma2(wo[7], p3.y, oB);

        u64 Ai = fadd2(iA, iB);
        u64 Af = fadd2(fA, fB);
        u64 Ag = fadd2(gA, gB);
        u64 Ao = fadd2(oA, oB);

        float ai0, ai1, af0, af1, ag0, ag1, ao0, ao1;
        upk2(Ai, ai0, ai1);
        upk2(Af, af0, af1);
        upk2(Ag, ag0, ag1);
        upk2(Ao, ao0, ao1);

        // Activations: 8 MUFU.TANH for gates (+2 for tanh(c) below)
        float ti0 = tanhap_(ai0), ti1 = tanhap_(ai1);
        float tf0 = tanhap_(af0), tf1 = tanhap_(af1);
        float tg0 = tanhap_(ag0), tg1 = tanhap_(ag1);
        float to0 = tanhap_(ao0), to1 = tanhap_(ao1);

        float s_i0 = fmaf(0.5f, ti0, 0.5f), s_i1 = fmaf(0.5f, ti1, 0.5f);
        float s_f0 = fmaf(0.5f, tf0, 0.5f), s_f1 = fmaf(0.5f, tf1, 0.5f);
        float s_o0 = fmaf(0.5f, to0, 0.5f), s_o1 = fmaf(0.5f, to1, 0.5f);

        c_0 = fmaf(s_f0, c_0, s_i0 * tg0);
        c_1 = fmaf(s_f1, c_1, s_i1 * tg1);
        h_0 = s_o0 * tanhap_(c_0);
        h_1 = s_o1 * tanhap_(c_1);

        ulonglong2 hh;
        hh.x = pk2(h_0, h_0);
        hh.y = pk2(h_1, h_1);
        *(ulonglong2*)&sh[rd ^ 1][g][o0] = hh;
        __syncwarp();

        xpi = ni; xpf = nf; xpg = ng; xpo = no;
    };

    #pragma unroll 1
    for (int s = 0; s < SEQ; s += 4) {
        dostep(xa, 0);  xa = ldx(s + 5);
        dostep(xb, 1);  xb = ldx(s + 6);
        dostep(xc, 0);  xc = ldx(s + 7);
        dostep(xd, 1);  xd = ldx(s + 8);
    }

    *(float2*)&out[b * HID + o0] = make_float2(h_0, h_1);
}

extern "C" void kernel_launch(void* const* d_in, const int* in_sizes, int n_in,
                              void* d_out, int out_size) {
    const float* x    = (const float*)d_in[0];
    const float* h0   = (const float*)d_in[1];
    const float* c0   = (const float*)d_in[2];
    const float* W_ih = (const float*)d_in[3];
    const float* W_hh = (const float*)d_in[4];
    const float* b_ih = (const float*)d_in[5];
    const float* b_hh = (const float*)d_in[6];
    lstm_kernel<<<CTAS, TPB>>>(x, h0, c0, W_ih, W_hh, b_ih, b_hh, (float*)d_out);
}

// round 9
// speedup vs baseline: 1.1609x; 1.1609x over previous
#include <cuda_runtime.h>

#define SEQ   4096
#define BATCH 4096
#define NIN   2
#define HID   8
#define CTAS  128
#define BPC   (BATCH / CTAS)   // 32 batches per CTA
#define TPB   (BPC * HID)      // 256 threads

typedef unsigned long long u64;

// MUFU.TANH: single-instruction tanh (sm_75+), max abs err ~2^-10.7
__device__ __forceinline__ float tanhap_(float x) {
    float y; asm("tanh.approx.f32 %0, %1;" : "=f"(y) : "f"(x)); return y;
}

// Pack two floats into a b64 register pair.
__device__ __forceinline__ u64 pk2(float lo, float hi) {
    u64 d;
    asm("mov.b64 %0, {%1, %2};" : "=l"(d)
        : "r"(__float_as_uint(lo)), "r"(__float_as_uint(hi)));
    return d;
}
__device__ __forceinline__ void upk2(u64 v, float& lo, float& hi) {
    unsigned a, b;
    asm("mov.b64 {%0, %1}, %2;" : "=r"(a), "=r"(b) : "l"(v));
    lo = __uint_as_float(a); hi = __uint_as_float(b);
}

// Packed fp32x2 ops on b64 carriers — single SASS instruction each.
__device__ __forceinline__ u64 ffma2(u64 a, u64 b, u64 c) {
    u64 d; asm("fma.rn.f32x2 %0, %1, %2, %3;" : "=l"(d) : "l"(a), "l"(b), "l"(c)); return d;
}
__device__ __forceinline__ u64 fmul2(u64 a, u64 b) {
    u64 d; asm("mul.rn.f32x2 %0, %1, %2;" : "=l"(d) : "l"(a), "l"(b)); return d;
}
__device__ __forceinline__ u64 fadd2(u64 a, u64 b) {
    u64 d; asm("add.rn.f32x2 %0, %1, %2;" : "=l"(d) : "l"(a), "l"(b)); return d;
}

// Compiler-only memory fence: orders smem STS/LDS in the instruction stream
// without emitting WARPSYNC. Loop body has no divergent branches, so the warp
// runs in physical lockstep; the >=12-instruction gap between the STS and the
// next step's LDS covers smem commit latency.
__device__ __forceinline__ void memfence_compiler() {
    asm volatile("" ::: "memory");
}

__global__ void __launch_bounds__(TPB) lstm_kernel(
    const float* __restrict__ x,
    const float* __restrict__ h0,
    const float* __restrict__ c0,
    const float* __restrict__ W_ih,
    const float* __restrict__ W_hh,
    const float* __restrict__ b_ih,
    const float* __restrict__ b_hh,
    float* __restrict__ out)
{
    const int tid = threadIdx.x;
    const int g   = tid >> 3;   // batch group within CTA
    const int j   = tid & 7;    // h index within batch
    const int b   = blockIdx.x * BPC + g;

    // Gate rows owned by this lane (PyTorch order i,f,g,o)
    const int ri = j, rf = 8 + j, rg = 16 + j, ro = 24 + j;
    // Activation plan (all via single-instruction MUFU.TANH):
    //   sigmoid(u) = 0.5*tanh(u/2) + 0.5  -> fold the 1/2 into rows i,f,o
    //   tanh(u)                            -> row g unscaled
    const float si = 0.5f, sf = 0.5f, sg = 1.0f, so = 0.5f;

    // Pair-packed weights as b64 carriers: (i,g) pair and (f,o) pair.
    // i and g feed the early part of the tail; f is needed last (1-FMA path).
    u64 wig_h[HID], wfo_h[HID];
    #pragma unroll
    for (int k = 0; k < HID; k++) {
        wig_h[k] = pk2(si * W_hh[ri * HID + k], sg * W_hh[rg * HID + k]);
        wfo_h[k] = pk2(sf * W_hh[rf * HID + k], so * W_hh[ro * HID + k]);
    }
    const u64 wig_x0 = pk2(si * W_ih[ri * NIN + 0], sg * W_ih[rg * NIN + 0]);
    const u64 wig_x1 = pk2(si * W_ih[ri * NIN + 1], sg * W_ih[rg * NIN + 1]);
    const u64 wfo_x0 = pk2(sf * W_ih[rf * NIN + 0], so * W_ih[ro * NIN + 0]);
    const u64 wfo_x1 = pk2(sf * W_ih[rf * NIN + 1], so * W_ih[ro * NIN + 1]);
    const u64 big = pk2(si * (b_ih[ri] + b_hh[ri]), sg * (b_ih[rg] + b_hh[rg]));
    const u64 bfo = pk2(sf * (b_ih[rf] + b_hh[rf]), so * (b_ih[ro] + b_hh[ro]));

    // h exchange: duplicated (h,h) pairs as u64, LDS.128 yields two ready
    // f32x2 multiplicands. Double-buffered; all traffic is intra-warp.
    __shared__ __align__(16) u64 sh[2][BPC][HID];

    float c = c0[b * HID + j];
    float h = h0[b * HID + j];
    sh[0][g][j] = pk2(h, h);
    __syncwarp();

    const size_t xstride = (size_t)BATCH * NIN;
    const float* xbase = x + (size_t)b * NIN;
    auto ldx = [&](int s) -> float2 {
        int sc = s < SEQ ? s : (SEQ - 1);
        return *(const float2*)(xbase + (size_t)sc * xstride);
    };

    // x-projection (bias + W_ih*x), computed off the recurrence chain.
    auto xproj = [&](float2 xv, u64& pig, u64& pfo) {
        u64 x0d = pk2(xv.x, xv.x);
        u64 x1d = pk2(xv.y, xv.y);
        pig = ffma2(wig_x1, x1d, ffma2(wig_x0, x0d, big));
        pfo = ffma2(wfo_x1, x1d, ffma2(wfo_x0, x0d, bfo));
    };

    float2 xa = ldx(1), xb = ldx(2), xc = ldx(3), xd = ldx(4);
    u64 xpig, xpfo;
    xproj(ldx(0), xpig, xpfo);

    auto dostep = [&](float2 xnext, int rd) {
        // LDS at the very top: reads buffer written >=12 instructions ago
        // (xproj of previous step sits between the STS and this LDS).
        const ulonglong2* hp = (const ulonglong2*)&sh[rd][g][0];
        ulonglong2 p0 = hp[0], p1 = hp[1], p2 = hp[2], p3 = hp[3];

        // Off-chain: half*c for the re-associated cell update.
        float hc = 0.5f * c;

        // Two balanced accumulation trees per gate-pair (pure FFMA2)
        u64 aA = ffma2(wig_h[0], p0.x, xpig);
        u64 gA = ffma2(wfo_h[0], p0.x, xpfo);
        u64 aB = fmul2(wig_h[1], p0.y);
        u64 gB = fmul2(wfo_h[1], p0.y);
        aA = ffma2(wig_h[2], p1.x, aA);  gA = ffma2(wfo_h[2], p1.x, gA);
        aB = ffma2(wig_h[3], p1.y, aB);  gB = ffma2(wfo_h[3], p1.y, gB);
        aA = ffma2(wig_h[4], p2.x, aA);  gA = ffma2(wfo_h[4], p2.x, gA);
        aB = ffma2(wig_h[5], p2.y, aB);  gB = ffma2(wfo_h[5], p2.y, gB);
        aA = ffma2(wig_h[6], p3.x, aA);  gA = ffma2(wfo_h[6], p3.x, gA);
        aB = ffma2(wig_h[7], p3.y, aB);  gB = ffma2(wfo_h[7], p3.y, gB);
        u64 Aig = fadd2(aA, aB);
        u64 Afo = fadd2(gA, gB);

        float a_i, a_g, a_f, a_o;
        upk2(Aig, a_i, a_g);
        upk2(Afo, a_f, a_o);

        // TANH issue order i, g, f, o: t_f (1-FMA path to c) arrives last.
        float t_i = tanhap_(a_i);   // a_i = u_i/2
        float t_g = tanhap_(a_g);   // true tanh(g)
        float t_f = tanhap_(a_f);
        float t_o = tanhap_(a_o);

        // c = 0.5*t_f*c + (0.5*c + s_i*t_g), s_i = 0.5*t_i + 0.5
        float s_i = fmaf(0.5f, t_i, 0.5f);
        float q   = fmaf(s_i, t_g, hc);     // 0.5*c + s_i*t_g
        c = fmaf(hc, t_f, q);
        float s_o = fmaf(0.5f, t_o, 0.5f);
        h = s_o * tanhap_(c);

        sh[rd ^ 1][g][j] = pk2(h, h);

        // Fill the STS-commit window with next step's x projection
        // (also gives the race-free gap before the next LDS).
        u64 nig, nfo;
        xproj(xnext, nig, nfo);
        xpig = nig; xpfo = nfo;

        memfence_compiler();   // order STS before next step's LDS, no WARPSYNC
    };

    #pragma unroll 1
    for (int s = 0; s < SEQ; s += 4) {
        dostep(xa, 0);  xa = ldx(s + 5);
        dostep(xb, 1);  xb = ldx(s + 6);
        dostep(xc, 0);  xc = ldx(s + 7);
        dostep(xd, 1);  xd = ldx(s + 8);
    }

    out[b * HID + j] = h;
}

extern "C" void kernel_launch(void* const* d_in, const int* in_sizes, int n_in,
                              void* d_out, int out_size) {
    const float* x    = (const float*)d_in[0];
    const float* h0   = (const float*)d_in[1];
    const float* c0   = (const float*)d_in[2];
    const float* W_ih = (const float*)d_in[3];
    const float* W_hh = (const float*)d_in[4];
    const float* b_ih = (const float*)d_in[5];
    const float* b_hh = (const float*)d_in[6];
    lstm_kernel<<<CTAS, TPB>>>(x, h0, c0, W_ih, W_hh, b_ih, b_hh, (float*)d_out);
}

// round 10
// speedup vs baseline: 1.1653x; 1.0038x over previous
#include <cuda_runtime.h>

#define SEQ   4096
#define BATCH 4096
#define NIN   2
#define HID   8
#define CTAS  128
#define BPC   (BATCH / CTAS)   // 32 batches per CTA
#define TPB   (BPC * HID)      // 256 threads

typedef unsigned long long u64;

// MUFU.TANH: single-instruction tanh (sm_75+), max abs err ~2^-10.7
__device__ __forceinline__ float tanhap_(float x) {
    float y; asm("tanh.approx.f32 %0, %1;" : "=f"(y) : "f"(x)); return y;
}

// Pack two floats into a b64 register pair.
__device__ __forceinline__ u64 pk2(float lo, float hi) {
    u64 d;
    asm("mov.b64 %0, {%1, %2};" : "=l"(d)
        : "r"(__float_as_uint(lo)), "r"(__float_as_uint(hi)));
    return d;
}
__device__ __forceinline__ void upk2(u64 v, float& lo, float& hi) {
    unsigned a, b;
    asm("mov.b64 {%0, %1}, %2;" : "=r"(a), "=r"(b) : "l"(v));
    lo = __uint_as_float(a); hi = __uint_as_float(b);
}

// Packed fp32x2 ops on b64 carriers — single SASS instruction each.
__device__ __forceinline__ u64 ffma2(u64 a, u64 b, u64 c) {
    u64 d; asm("fma.rn.f32x2 %0, %1, %2, %3;" : "=l"(d) : "l"(a), "l"(b), "l"(c)); return d;
}
__device__ __forceinline__ u64 fmul2(u64 a, u64 b) {
    u64 d; asm("mul.rn.f32x2 %0, %1, %2;" : "=l"(d) : "l"(a), "l"(b)); return d;
}
__device__ __forceinline__ u64 fadd2(u64 a, u64 b) {
    u64 d; asm("add.rn.f32x2 %0, %1, %2;" : "=l"(d) : "l"(a), "l"(b)); return d;
}

__global__ void __launch_bounds__(TPB) lstm_kernel(
    const float* __restrict__ x,
    const float* __restrict__ h0,
    const float* __restrict__ c0,
    const float* __restrict__ W_ih,
    const float* __restrict__ W_hh,
    const float* __restrict__ b_ih,
    const float* __restrict__ b_hh,
    float* __restrict__ out)
{
    const int tid = threadIdx.x;
    const int g   = tid >> 3;   // batch group within CTA (8-lane segment)
    const int j   = tid & 7;    // h index within batch
    const int b   = blockIdx.x * BPC + g;

    // Gate rows owned by this lane (PyTorch order i,f,g,o)
    const int ri = j, rf = 8 + j, rg = 16 + j, ro = 24 + j;
    // Activation plan (all via single-instruction MUFU.TANH):
    //   sigmoid(u) = 0.5*tanh(u/2) + 0.5  -> fold the 1/2 into rows i,f,o
    //   tanh(u)                            -> row g unscaled
    const float si = 0.5f, sf = 0.5f, sg = 1.0f, so = 0.5f;

    // Pair-packed weights as b64 carriers: (i,g) pair and (f,o) pair.
    u64 wig_h[HID], wfo_h[HID];
    #pragma unroll
    for (int k = 0; k < HID; k++) {
        wig_h[k] = pk2(si * W_hh[ri * HID + k], sg * W_hh[rg * HID + k]);
        wfo_h[k] = pk2(sf * W_hh[rf * HID + k], so * W_hh[ro * HID + k]);
    }
    const u64 wig_x0 = pk2(si * W_ih[ri * NIN + 0], sg * W_ih[rg * NIN + 0]);
    const u64 wig_x1 = pk2(si * W_ih[ri * NIN + 1], sg * W_ih[rg * NIN + 1]);
    const u64 wfo_x0 = pk2(sf * W_ih[rf * NIN + 0], so * W_ih[ro * NIN + 0]);
    const u64 wfo_x1 = pk2(sf * W_ih[rf * NIN + 1], so * W_ih[ro * NIN + 1]);
    const u64 big = pk2(si * (b_ih[ri] + b_hh[ri]), sg * (b_ih[rg] + b_hh[rg]));
    const u64 bfo = pk2(sf * (b_ih[rf] + b_hh[rf]), so * (b_ih[ro] + b_hh[ro]));

    float c = c0[b * HID + j];
    float h = h0[b * HID + j];

    const size_t xstride = (size_t)BATCH * NIN;
    const float* xbase = x + (size_t)b * NIN;
    auto ldx = [&](int s) -> float2 {
        int sc = s < SEQ ? s : (SEQ - 1);
        return *(const float2*)(xbase + (size_t)sc * xstride);
    };

    // x-projection (bias + W_ih*x), computed off the recurrence chain.
    auto xproj = [&](float2 xv, u64& pig, u64& pfo) {
        u64 x0d = pk2(xv.x, xv.x);
        u64 x1d = pk2(xv.y, xv.y);
        pig = ffma2(wig_x1, x1d, ffma2(wig_x0, x0d, big));
        pfo = ffma2(wfo_x1, x1d, ffma2(wfo_x0, x0d, bfo));
    };

    float2 xa = ldx(1), xb = ldx(2), xc = ldx(3), xd = ldx(4);
    u64 xpig, xpfo;
    xproj(ldx(0), xpig, xpfo);

    const unsigned FULL = 0xffffffffu;

    auto dostep = [&](float2 xnext) {
        // 8-lane broadcast of h via width-8 shfl — no smem, no STS-commit
        // wait, no WARPSYNC. All 8 shfls are independent (same source reg).
        float e0 = __shfl_sync(FULL, h, 0, 8);
        float e1 = __shfl_sync(FULL, h, 1, 8);
        float e2 = __shfl_sync(FULL, h, 2, 8);
        float e3 = __shfl_sync(FULL, h, 3, 8);
        float e4 = __shfl_sync(FULL, h, 4, 8);
        float e5 = __shfl_sync(FULL, h, 5, 8);
        float e6 = __shfl_sync(FULL, h, 6, 8);
        float e7 = __shfl_sync(FULL, h, 7, 8);

        // Off-chain: half*c for the re-associated cell update.
        float hc = 0.5f * c;

        // Duplicated (h,h) pairs as f32x2 multiplicands (interleave w/ arrivals)
        u64 d0 = pk2(e0, e0), d1 = pk2(e1, e1);
        u64 d2 = pk2(e2, e2), d3 = pk2(e3, e3);
        u64 d4 = pk2(e4, e4), d5 = pk2(e5, e5);
        u64 d6 = pk2(e6, e6), d7 = pk2(e7, e7);

        // Two balanced accumulation trees per gate-pair (pure FFMA2)
        u64 aA = ffma2(wig_h[0], d0, xpig);
        u64 gA = ffma2(wfo_h[0], d0, xpfo);
        u64 aB = fmul2(wig_h[1], d1);
        u64 gB = fmul2(wfo_h[1], d1);
        aA = ffma2(wig_h[2], d2, aA);  gA = ffma2(wfo_h[2], d2, gA);
        aB = ffma2(wig_h[3], d3, aB);  gB = ffma2(wfo_h[3], d3, gB);
        aA = ffma2(wig_h[4], d4, aA);  gA = ffma2(wfo_h[4], d4, gA);
        aB = ffma2(wig_h[5], d5, aB);  gB = ffma2(wfo_h[5], d5, gB);
        aA = ffma2(wig_h[6], d6, aA);  gA = ffma2(wfo_h[6], d6, gA);
        aB = ffma2(wig_h[7], d7, aB);  gB = ffma2(wfo_h[7], d7, gB);
        u64 Aig = fadd2(aA, aB);
        u64 Afo = fadd2(gA, gB);

        float a_i, a_g, a_f, a_o;
        upk2(Aig, a_i, a_g);
        upk2(Afo, a_f, a_o);

        // TANH issue order i, g, f, o: t_f (1-FMA path to c) arrives last.
        float t_i = tanhap_(a_i);   // a_i = u_i/2
        float t_g = tanhap_(a_g);   // true tanh(g)
        float t_f = tanhap_(a_f);
        float t_o = tanhap_(a_o);

        // c = 0.5*t_f*c + (0.5*c + s_i*t_g), s_i = 0.5*t_i + 0.5
        float s_i = fmaf(0.5f, t_i, 0.5f);
        float q   = fmaf(s_i, t_g, hc);
        c = fmaf(hc, t_f, q);
        float s_o = fmaf(0.5f, t_o, 0.5f);
        h = s_o * tanhap_(c);       // h feeds next step's shfl directly

        // Next step's x projection (off the recurrence chain)
        u64 nig, nfo;
        xproj(xnext, nig, nfo);
        xpig = nig; xpfo = nfo;
    };

    #pragma unroll 1
    for (int s = 0; s < SEQ; s += 4) {
        dostep(xa);  xa = ldx(s + 5);
        dostep(xb);  xb = ldx(s + 6);
        dostep(xc);  xc = ldx(s + 7);
        dostep(xd);  xd = ldx(s + 8);
    }

    out[b * HID + j] = h;
}

extern "C" void kernel_launch(void* const* d_in, const int* in_sizes, int n_in,
                              void* d_out, int out_size) {
    const float* x    = (const float*)d_in[0];
    const float* h0   = (const float*)d_in[1];
    const float* c0   = (const float*)d_in[2];
    const float* W_ih = (const float*)d_in[3];
    const float* W_hh = (const float*)d_in[4];
    const float* b_ih = (const float*)d_in[5];
    const float* b_hh = (const float*)d_in[6];
    lstm_kernel<<<CTAS, TPB>>>(x, h0, c0, W_ih, W_hh, b_ih, b_hh, (float*)d_out);
}

// round 11
// speedup vs baseline: 1.4744x; 1.2653x over previous
#include <cuda_runtime.h>

#define SEQ   4096
#define BATCH 4096
#define NIN   2
#define HID   8
#define CTAS  128
#define BPC   (BATCH / CTAS)   // 32 batches per CTA
#define TPB   (BPC * HID)      // 256 threads

typedef unsigned long long u64;

// MUFU.TANH: single-instruction tanh (sm_75+), max abs err ~2^-10.7
__device__ __forceinline__ float tanhap_(float x) {
    float y; asm("tanh.approx.f32 %0, %1;" : "=f"(y) : "f"(x)); return y;
}

// Pack two floats into a b64 register pair.
__device__ __forceinline__ u64 pk2(float lo, float hi) {
    u64 d;
    asm("mov.b64 %0, {%1, %2};" : "=l"(d)
        : "r"(__float_as_uint(lo)), "r"(__float_as_uint(hi)));
    return d;
}
__device__ __forceinline__ void upk2(u64 v, float& lo, float& hi) {
    unsigned a, b;
    asm("mov.b64 {%0, %1}, %2;" : "=r"(a), "=r"(b) : "l"(v));
    lo = __uint_as_float(a); hi = __uint_as_float(b);
}

// Packed fp32x2 ops on b64 carriers — single SASS instruction each.
__device__ __forceinline__ u64 ffma2(u64 a, u64 b, u64 c) {
    u64 d; asm("fma.rn.f32x2 %0, %1, %2, %3;" : "=l"(d) : "l"(a), "l"(b), "l"(c)); return d;
}
__device__ __forceinline__ u64 fmul2(u64 a, u64 b) {
    u64 d; asm("mul.rn.f32x2 %0, %1, %2;" : "=l"(d) : "l"(a), "l"(b)); return d;
}
__device__ __forceinline__ u64 fadd2(u64 a, u64 b) {
    u64 d; asm("add.rn.f32x2 %0, %1, %2;" : "=l"(d) : "l"(a), "l"(b)); return d;
}

// Compiler-only memory fence (no WARPSYNC emitted). Same-warp LSU ordering
// guarantees the hoisted LDS sees all lanes' preceding STS (proven in R9).
__device__ __forceinline__ void memfence_compiler() {
    asm volatile("" ::: "memory");
}

__global__ void __launch_bounds__(TPB) lstm_kernel(
    const float* __restrict__ x,
    const float* __restrict__ h0,
    const float* __restrict__ c0,
    const float* __restrict__ W_ih,
    const float* __restrict__ W_hh,
    const float* __restrict__ b_ih,
    const float* __restrict__ b_hh,
    float* __restrict__ out)
{
    const int tid = threadIdx.x;
    const int g   = tid >> 3;   // batch group within CTA
    const int j   = tid & 7;    // h index within batch
    const int b   = blockIdx.x * BPC + g;

    // Gate rows owned by this lane (PyTorch order i,f,g,o)
    const int ri = j, rf = 8 + j, rg = 16 + j, ro = 24 + j;
    // Activation plan (all via single-instruction MUFU.TANH):
    //   sigmoid(u) = 0.5*tanh(u/2) + 0.5  -> fold the 1/2 into rows i,f,o
    //   tanh(u)                            -> row g unscaled
    const float si = 0.5f, sf = 0.5f, sg = 1.0f, so = 0.5f;

    // Pair-packed weights as b64 carriers: (i,g) pair and (f,o) pair.
    u64 wig_h[HID], wfo_h[HID];
    #pragma unroll
    for (int k = 0; k < HID; k++) {
        wig_h[k] = pk2(si * W_hh[ri * HID + k], sg * W_hh[rg * HID + k]);
        wfo_h[k] = pk2(sf * W_hh[rf * HID + k], so * W_hh[ro * HID + k]);
    }
    const u64 wig_x0 = pk2(si * W_ih[ri * NIN + 0], sg * W_ih[rg * NIN + 0]);
    const u64 wig_x1 = pk2(si * W_ih[ri * NIN + 1], sg * W_ih[rg * NIN + 1]);
    const u64 wfo_x0 = pk2(sf * W_ih[rf * NIN + 0], so * W_ih[ro * NIN + 0]);
    const u64 wfo_x1 = pk2(sf * W_ih[rf * NIN + 1], so * W_ih[ro * NIN + 1]);
    const u64 big = pk2(si * (b_ih[ri] + b_hh[ri]), sg * (b_ih[rg] + b_hh[rg]));
    const u64 bfo = pk2(sf * (b_ih[rf] + b_hh[rf]), so * (b_ih[ro] + b_hh[ro]));

    // h exchange: duplicated (h,h) pairs. SINGLE buffer: each step's LDS is
    // issued immediately after the same warp's STS (same-warp LSU ordering),
    // software-pipelined one step ahead so the LDS round-trip overlaps the
    // step tail + xproj + loop overhead instead of sitting on the chain head.
    __shared__ __align__(16) u64 sh[BPC][HID];

    float c = c0[b * HID + j];
    float h = h0[b * HID + j];

    const size_t xstride = (size_t)BATCH * NIN;
    const float* xbase = x + (size_t)b * NIN;
    auto ldx = [&](int s) -> float2 {
        int sc = s < SEQ ? s : (SEQ - 1);
        return *(const float2*)(xbase + (size_t)sc * xstride);
    };

    // x-projection (bias + W_ih*x), computed off the recurrence chain.
    auto xproj = [&](float2 xv, u64& pig, u64& pfo) {
        u64 x0d = pk2(xv.x, xv.x);
        u64 x1d = pk2(xv.y, xv.y);
        pig = ffma2(wig_x1, x1d, ffma2(wig_x0, x0d, big));
        pfo = ffma2(wfo_x1, x1d, ffma2(wfo_x0, x0d, bfo));
    };

    // Prologue: publish h(0), pre-load the pipeline registers.
    sh[g][j] = pk2(h, h);
    __syncwarp();
    ulonglong2 P0, P1, P2, P3;
    {
        const ulonglong2* hp = (const ulonglong2*)&sh[g][0];
        P0 = hp[0]; P1 = hp[1]; P2 = hp[2]; P3 = hp[3];
    }

    float2 xa = ldx(1), xb = ldx(2), xc = ldx(3), xd = ldx(4);
    u64 xpig, xpfo;
    xproj(ldx(0), xpig, xpfo);

    auto dostep = [&](float2 xnext) {
        // Consume the h pairs loaded at the END of the previous step —
        // their LDS round-trip has been in flight across the step boundary.
        ulonglong2 p0 = P0, p1 = P1, p2 = P2, p3 = P3;

        // Off-chain: half*c for the re-associated cell update.
        float hc = 0.5f * c;

        // Two balanced accumulation trees per gate-pair (pure FFMA2)
        u64 aA = ffma2(wig_h[0], p0.x, xpig);
        u64 gA = ffma2(wfo_h[0], p0.x, xpfo);
        u64 aB = fmul2(wig_h[1], p0.y);
        u64 gB = fmul2(wfo_h[1], p0.y);
        aA = ffma2(wig_h[2], p1.x, aA);  gA = ffma2(wfo_h[2], p1.x, gA);
        aB = ffma2(wig_h[3], p1.y, aB);  gB = ffma2(wfo_h[3], p1.y, gB);
        aA = ffma2(wig_h[4], p2.x, aA);  gA = ffma2(wfo_h[4], p2.x, gA);
        aB = ffma2(wig_h[5], p2.y, aB);  gB = ffma2(wfo_h[5], p2.y, gB);
        aA = ffma2(wig_h[6], p3.x, aA);  gA = ffma2(wfo_h[6], p3.x, gA);
        aB = ffma2(wig_h[7], p3.y, aB);  gB = ffma2(wfo_h[7], p3.y, gB);
        u64 Aig = fadd2(aA, aB);
        u64 Afo = fadd2(gA, gB);

        float a_i, a_g, a_f, a_o;
        upk2(Aig, a_i, a_g);
        upk2(Afo, a_f, a_o);

        // Gate activations: one batched MUFU round-trip.
        float t_i = tanhap_(a_i);   // a_i = u_i/2
        float t_g = tanhap_(a_g);   // true tanh(g)
        float t_f = tanhap_(a_f);
        float t_o = tanhap_(a_o);

        // c = 0.5*t_f*c + (0.5*c + s_i*t_g), s_i = 0.5*t_i + 0.5
        float s_i = fmaf(0.5f, t_i, 0.5f);
        float q   = fmaf(s_i, t_g, hc);
        c = fmaf(hc, t_f, q);
        float s_o = fmaf(0.5f, t_o, 0.5f);
        h = s_o * tanhap_(c);       // second MUFU round-trip

        // Publish h and IMMEDIATELY issue next step's exchange loads:
        // the LDS round-trip overlaps xproj + ldx + loop overhead.
        sh[g][j] = pk2(h, h);
        memfence_compiler();
        {
            const ulonglong2* hp = (const ulonglong2*)&sh[g][0];
            P0 = hp[0]; P1 = hp[1]; P2 = hp[2]; P3 = hp[3];
        }

        // Fill window: next step's x projection (off the recurrence chain)
        u64 nig, nfo;
        xproj(xnext, nig, nfo);
        xpig = nig; xpfo = nfo;
    };

    #pragma unroll 1
    for (int s = 0; s < SEQ; s += 4) {
        dostep(xa);  xa = ldx(s + 5);
        dostep(xb);  xb = ldx(s + 6);
        dostep(xc);  xc = ldx(s + 7);
        dostep(xd);  xd = ldx(s + 8);
    }

    out[b * HID + j] = h;
}

extern "C" void kernel_launch(void* const* d_in, const int* in_sizes, int n_in,
                              void* d_out, int out_size) {
    const float* x    = (const float*)d_in[0];
    const float* h0   = (const float*)d_in[1];
    const float* c0   = (const float*)d_in[2];
    const float* W_ih = (const float*)d_in[3];
    const float* W_hh = (const float*)d_in[4];
    const float* b_ih = (const float*)d_in[5];
    const float* b_hh = (const float*)d_in[6];
    lstm_kernel<<<CTAS, TPB>>>(x, h0, c0, W_ih, W_hh, b_ih, b_hh, (float*)d_out);
}

// round 13
// speedup vs baseline: 1.5680x; 1.0635x over previous
#include <cuda_runtime.h>

#define SEQ   4096
#define BATCH 4096
#define NIN   2
#define HID   8
#define CTAS  128
#define BPC   (BATCH / CTAS)   // 32 batches per CTA
#define TPB   (BPC * HID)      // 256 threads

typedef unsigned long long u64;

// MUFU.TANH: single-instruction tanh (sm_75+), max abs err ~2^-10.7
__device__ __forceinline__ float tanhap_(float x) {
    float y; asm("tanh.approx.f32 %0, %1;" : "=f"(y) : "f"(x)); return y;
}

// Pack two floats into a b64 register pair.
__device__ __forceinline__ u64 pk2(float lo, float hi) {
    u64 d;
    asm("mov.b64 %0, {%1, %2};" : "=l"(d)
        : "r"(__float_as_uint(lo)), "r"(__float_as_uint(hi)));
    return d;
}
__device__ __forceinline__ void upk2(u64 v, float& lo, float& hi) {
    unsigned a, b;
    asm("mov.b64 {%0, %1}, %2;" : "=r"(a), "=r"(b) : "l"(v));
    lo = __uint_as_float(a); hi = __uint_as_float(b);
}

// Packed fp32x2 ops on b64 carriers — single SASS instruction each.
__device__ __forceinline__ u64 ffma2(u64 a, u64 b, u64 c) {
    u64 d; asm("fma.rn.f32x2 %0, %1, %2, %3;" : "=l"(d) : "l"(a), "l"(b), "l"(c)); return d;
}
__device__ __forceinline__ u64 fmul2(u64 a, u64 b) {
    u64 d; asm("mul.rn.f32x2 %0, %1, %2;" : "=l"(d) : "l"(a), "l"(b)); return d;
}
__device__ __forceinline__ u64 fadd2(u64 a, u64 b) {
    u64 d; asm("add.rn.f32x2 %0, %1, %2;" : "=l"(d) : "l"(a), "l"(b)); return d;
}

// Compiler-only memory fence (no WARPSYNC emitted). Same-warp LSU ordering
// guarantees the hoisted LDS sees all lanes' preceding STS (proven R9/R11).
__device__ __forceinline__ void memfence_compiler() {
    asm volatile("" ::: "memory");
}

__global__ void __launch_bounds__(TPB) lstm_kernel(
    const float* __restrict__ x,
    const float* __restrict__ h0,
    const float* __restrict__ c0,
    const float* __restrict__ W_ih,
    const float* __restrict__ W_hh,
    const float* __restrict__ b_ih,
    const float* __restrict__ b_hh,
    float* __restrict__ out)
{
    const int tid = threadIdx.x;
    const int g   = tid >> 3;   // batch group within CTA
    const int j   = tid & 7;    // h index within batch
    const int b   = blockIdx.x * BPC + g;

    // Gate rows owned by this lane (PyTorch order i,f,g,o)
    const int ri = j, rf = 8 + j, rg = 16 + j, ro = 24 + j;
    // sigmoid(u) = 0.5*tanh(u/2)+0.5 -> fold the 1/2 into rows i,f,o.
    const float si = 0.5f, sf = 0.5f, sg = 1.0f, so = 0.5f;

    // Pair-packed weights as b64 carriers: (i,g) pair and (f,o) pair.
    u64 wig_h[HID], wfo_h[HID];
    #pragma unroll
    for (int k = 0; k < HID; k++) {
        wig_h[k] = pk2(si * W_hh[ri * HID + k], sg * W_hh[rg * HID + k]);
        wfo_h[k] = pk2(sf * W_hh[rf * HID + k], so * W_hh[ro * HID + k]);
    }
    const u64 wig_x0 = pk2(si * W_ih[ri * NIN + 0], sg * W_ih[rg * NIN + 0]);
    const u64 wig_x1 = pk2(si * W_ih[ri * NIN + 1], sg * W_ih[rg * NIN + 1]);
    const u64 wfo_x0 = pk2(sf * W_ih[rf * NIN + 0], so * W_ih[ro * NIN + 0]);
    const u64 wfo_x1 = pk2(sf * W_ih[rf * NIN + 1], so * W_ih[ro * NIN + 1]);
    const u64 big = pk2(si * (b_ih[ri] + b_hh[ri]), sg * (b_ih[rg] + b_hh[rg]));
    const u64 bfo = pk2(sf * (b_ih[rf] + b_hh[rf]), so * (b_ih[ro] + b_hh[ro]));

    // h exchange: duplicated (h,h) pairs, SINGLE buffer, software-pipelined
    // one step ahead (LDS issued right after the STS; consumed next step).
    __shared__ __align__(16) u64 sh[BPC][HID];

    float c = c0[b * HID + j];
    float h = h0[b * HID + j];

    const size_t xstride = (size_t)BATCH * NIN;
    const float* xbase = x + (size_t)b * NIN;
    auto ldx = [&](int s) -> float2 {
        int sc = s < SEQ ? s : (SEQ - 1);
        return *(const float2*)(xbase + (size_t)sc * xstride);
    };

    // x-projection (bias + W_ih*x), off the recurrence chain.
    auto xproj = [&](float2 xv, u64& pig, u64& pfo) {
        u64 x0d = pk2(xv.x, xv.x);
        u64 x1d = pk2(xv.y, xv.y);
        pig = ffma2(wig_x1, x1d, ffma2(wig_x0, x0d, big));
        pfo = ffma2(wfo_x1, x1d, ffma2(wfo_x0, x0d, bfo));
    };

    // Prologue: publish h(0), pre-load pipeline registers.
    sh[g][j] = pk2(h, h);
    __syncwarp();
    ulonglong2 P0, P1, P2, P3;
    {
        const ulonglong2* hp = (const ulonglong2*)&sh[g][0];
        P0 = hp[0]; P1 = hp[1]; P2 = hp[2]; P3 = hp[3];
    }

    // 8-deep x prefetch for the 8x-unrolled loop.
    float2 xq0 = ldx(1), xq1 = ldx(2), xq2 = ldx(3), xq3 = ldx(4);
    float2 xq4 = ldx(5), xq5 = ldx(6), xq6 = ldx(7), xq7 = ldx(8);
    u64 xpig, xpfo;
    xproj(ldx(0), xpig, xpfo);

    auto dostep = [&](float2 xnext) {
        // Consume h pairs whose LDS was issued at the end of the previous step.
        ulonglong2 p0 = P0, p1 = P1, p2 = P2, p3 = P3;

        float hc = 0.5f * c;   // off-chain half*c

        // FOUR-way accumulation trees per gate-pair: depth 2 FFMA2 + 2 fadd2
        // (~16 cyc) instead of the 5-deep chain (~24 cyc).
        u64 aA = ffma2(wig_h[0], p0.x, xpig);
        u64 gA = ffma2(wfo_h[0], p0.x, xpfo);
        u64 aB = fmul2(wig_h[1], p0.y);
        u64 gB = fmul2(wfo_h[1], p0.y);
        u64 aC = fmul2(wig_h[2], p1.x);
        u64 gC = fmul2(wfo_h[2], p1.x);
        u64 aD = fmul2(wig_h[3], p1.y);
        u64 gD = fmul2(wfo_h[3], p1.y);
        aA = ffma2(wig_h[4], p2.x, aA);  gA = ffma2(wfo_h[4], p2.x, gA);
        aB = ffma2(wig_h[5], p2.y, aB);  gB = ffma2(wfo_h[5], p2.y, gB);
        aC = ffma2(wig_h[6], p3.x, aC);  gC = ffma2(wfo_h[6], p3.x, gC);
        aD = ffma2(wig_h[7], p3.y, aD);  gD = ffma2(wfo_h[7], p3.y, gD);
        u64 aAB = fadd2(aA, aB);
        u64 gAB = fadd2(gA, gB);
        u64 aCD = fadd2(aC, aD);
        u64 gCD = fadd2(gC, gD);
        u64 Aig = fadd2(aAB, aCD);
        u64 Afo = fadd2(gAB, gCD);

        float a_i, a_g, a_f, a_o;
        upk2(Aig, a_i, a_g);
        upk2(Afo, a_f, a_o);

        // Gate tanhs, issue order i,g,f,o: c waits only on t_f, with s_i/q
        // computed while t_f's scoreboard drains. t_o is off the c-chain.
        float t_i = tanhap_(a_i);   // a_i = u_i/2
        float t_g = tanhap_(a_g);   // true tanh(g)
        float t_f = tanhap_(a_f);
        float t_o = tanhap_(a_o);

        float s_i = fmaf(0.5f, t_i, 0.5f);
        float q   = fmaf(s_i, t_g, hc);
        c = fmaf(hc, t_f, q);
        float s_o = fmaf(0.5f, t_o, 0.5f);
        h = s_o * tanhap_(c);       // second MUFU round-trip

        // Publish h and IMMEDIATELY issue next step's exchange loads;
        // the LDS round-trip overlaps xproj + loop overhead (proven R11).
        sh[g][j] = pk2(h, h);
        memfence_compiler();
        {
            const ulonglong2* hp = (const ulonglong2*)&sh[g][0];
            P0 = hp[0]; P1 = hp[1]; P2 = hp[2]; P3 = hp[3];
        }

        // Fill window: next step's x projection (off the recurrence chain)
        u64 nig, nfo;
        xproj(xnext, nig, nfo);
        xpig = nig; xpfo = nfo;
    };

    #pragma unroll 1
    for (int s = 0; s < SEQ; s += 8) {
        dostep(xq0);  xq0 = ldx(s + 9);
        dostep(xq1);  xq1 = ldx(s + 10);
        dostep(xq2);  xq2 = ldx(s + 11);
        dostep(xq3);  xq3 = ldx(s + 12);
        dostep(xq4);  xq4 = ldx(s + 13);
        dostep(xq5);  xq5 = ldx(s + 14);
        dostep(xq6);  xq6 = ldx(s + 15);
        dostep(xq7);  xq7 = ldx(s + 16);
    }

    out[b * HID + j] = h;
}

extern "C" void kernel_launch(void* const* d_in, const int* in_sizes, int n_in,
                              void* d_out, int out_size) {
    const float* x    = (const float*)d_in[0];
    const float* h0   = (const float*)d_in[1];
    const float* c0   = (const float*)d_in[2];
    const float* W_ih = (const float*)d_in[3];
    const float* W_hh = (const float*)d_in[4];
    const float* b_ih = (const float*)d_in[5];
    const float* b_hh = (const float*)d_in[6];
    lstm_kernel<<<CTAS, TPB>>>(x, h0, c0, W_ih, W_hh, b_ih, b_hh, (float*)d_out);
}